// round 9
// baseline (speedup 1.0000x reference)
#include <cuda_runtime.h>
#include <cstdint>

#define NN   50000
#define EE   800000
#define BB   512
#define DIN  128
#define HH   64
#define DOUT 32

// ---------------- scratch (static device arrays; no allocation) ----------------
__device__ __align__(16) float d_z[NN * HH];    // z = x @ W1 (pre-aggregation)
__device__ __align__(16) float d_h[NN * HH];    // t = z_self + sum_nbr z (pre-BN)
__device__ __align__(16) float d_x[NN * HH];    // layer output
__device__ __align__(16) float d_pool[BB * HH]; // global add pool
__device__ __align__(16) float d_stats[2 * HH]; // colsum | colsumsq of t
__device__ int   d_deg[NN];
__device__ int   d_off[NN + 1];
__device__ int   d_cur[NN];
__device__ int   d_col[EE];         // CSR: src ids grouped by dst
__device__ int   d_src32[EE];       // normalized int32 edge endpoints
__device__ int   d_dst32[EE];
__device__ int   d_batch32[NN];     // normalized int32 graph ids
__device__ int   d_is64;            // 1 if index inputs are int64

// ---------------- dtype detection + normalization ----------------
// JAX may silently downcast the reference's int64 indices to int32
// (jax_enable_x64=False default). Detect which layout the buffer holds:
// genuine int64 node ids are < NN so every high word is 0; packed int32
// pairs read as int64 are >= 2^32 whenever the odd element is nonzero.
__global__ void k_detect(const void* __restrict__ ei) {
    const long long* p = (const long long*)ei;
    int ok = 1;
    for (int i = 0; i < 1024; i++) {          // 8 KB << buffer size, safe either way
        long long v = p[i];
        if (v < 0 || v >= NN) { ok = 0; break; }
    }
    d_is64 = ok;
}

__device__ __forceinline__ int clampi(int v, int hi) {
    return v < 0 ? 0 : (v >= hi ? hi - 1 : v);
}

__global__ void k_cvt(const void* __restrict__ ei, const void* __restrict__ batch) {
    int i = blockIdx.x * 256 + threadIdx.x;
    int is64 = d_is64;
    if (i < EE) {
        int s, d;
        if (is64) {
            s = (int)((const long long*)ei)[i];
            d = (int)((const long long*)ei)[EE + i];
        } else {
            s = ((const int*)ei)[i];
            d = ((const int*)ei)[EE + i];
        }
        // clamp: no-op on valid data; converts misinterpretation into a
        // measurable wrong answer instead of an illegal access.
        d_src32[i] = clampi(s, NN);
        d_dst32[i] = clampi(d, NN);
    }
    if (i < NN) {
        int b = is64 ? (int)((const long long*)batch)[i]
                     : ((const int*)batch)[i];
        d_batch32[i] = clampi(b, BB);
    }
}

// ---------------- CSR build ----------------
__global__ void k_zero() {
    int i = blockIdx.x * 256 + threadIdx.x;
    if (i < NN) d_deg[i] = 0;
    if (i < BB * HH) d_pool[i] = 0.f;
}

__global__ void k_hist() {
    int e = blockIdx.x * 256 + threadIdx.x;
    if (e < EE) atomicAdd(&d_deg[d_dst32[e]], 1);
}

__global__ void k_scan() {
    __shared__ int ssum[1024];
    int t = threadIdx.x;
    const int CH = (NN + 1023) / 1024;  // 49
    int start = t * CH;
    int s = 0;
    for (int i = 0; i < CH; i++) {
        int idx = start + i;
        if (idx < NN) s += d_deg[idx];
    }
    ssum[t] = s;
    __syncthreads();
    for (int off = 1; off < 1024; off <<= 1) {
        int v = (t >= off) ? ssum[t - off] : 0;
        __syncthreads();
        ssum[t] += v;
        __syncthreads();
    }
    int run = (t == 0) ? 0 : ssum[t - 1];
    for (int i = 0; i < CH; i++) {
        int idx = start + i;
        if (idx < NN) {
            d_off[idx] = run;
            d_cur[idx] = run;
            run += d_deg[idx];
        }
    }
    if (t == 1023) d_off[NN] = run;
}

__global__ void k_fill() {
    int e = blockIdx.x * 256 + threadIdx.x;
    if (e < EE) {
        int d = d_dst32[e];
        int p = atomicAdd(&d_cur[d], 1);
        d_col[p] = d_src32[e];
    }
}

// ---------------- GEMM A: z = x @ W1  (bias b1 cancels through BN) ----------------
template<int K, bool FROM_PARAM>
__global__ __launch_bounds__(256)
void k_gemmA(const float* __restrict__ xp, const float* __restrict__ W) {
    __shared__ float sW[K * HH];
    int tid = threadIdx.x;
    for (int i = tid; i < K * HH; i += 256) sW[i] = W[i];
    if (blockIdx.x == 0 && tid < 2 * HH) d_stats[tid] = 0.f;  // reset stats for this layer
    __syncthreads();

    int row = blockIdx.x * 256 + tid;
    if (row >= NN) return;
    const float* X = FROM_PARAM ? xp : d_x;

    float acc[HH];
#pragma unroll
    for (int c = 0; c < HH; c++) acc[c] = 0.f;

    const float4* Xr = (const float4*)(X + (size_t)row * K);
#pragma unroll 1
    for (int kc = 0; kc < K / 4; kc++) {
        float4 a = Xr[kc];
        const float* w0 = &sW[(4 * kc + 0) * HH];
        const float* w1 = &sW[(4 * kc + 1) * HH];
        const float* w2 = &sW[(4 * kc + 2) * HH];
        const float* w3 = &sW[(4 * kc + 3) * HH];
#pragma unroll
        for (int c = 0; c < HH; c++)
            acc[c] += a.x * w0[c] + a.y * w1[c] + a.z * w2[c] + a.w * w3[c];
    }

    float4* Zr = (float4*)(d_z + (size_t)row * HH);
#pragma unroll
    for (int cc = 0; cc < HH / 4; cc++)
        Zr[cc] = make_float4(acc[4 * cc], acc[4 * cc + 1], acc[4 * cc + 2], acc[4 * cc + 3]);
}

// ---------------- aggregation: t = z_self + sum_nbr z, plus BN stats ----------------
// 16 lanes per node (64 floats = 16 x float4 slots); grid = NN*16/256 = 3125 exact.
__global__ __launch_bounds__(256)
void k_agg() {
    __shared__ float sStat[2 * HH];
    int tid = threadIdx.x;
    if (tid < 2 * HH) sStat[tid] = 0.f;
    __syncthreads();

    int gt = blockIdx.x * 256 + tid;
    int node = gt >> 4;
    int slot = gt & 15;

    const float4* Z = (const float4*)d_z;
    float4 acc = Z[node * 16 + slot];  // self term (eps = 0)

    int e = d_off[node];
    int end = d_off[node + 1];
    for (; e + 3 < end; e += 4) {
        int c0 = d_col[e], c1 = d_col[e + 1], c2 = d_col[e + 2], c3 = d_col[e + 3];
        float4 v0 = Z[c0 * 16 + slot];
        float4 v1 = Z[c1 * 16 + slot];
        float4 v2 = Z[c2 * 16 + slot];
        float4 v3 = Z[c3 * 16 + slot];
        acc.x += (v0.x + v1.x) + (v2.x + v3.x);
        acc.y += (v0.y + v1.y) + (v2.y + v3.y);
        acc.z += (v0.z + v1.z) + (v2.z + v3.z);
        acc.w += (v0.w + v1.w) + (v2.w + v3.w);
    }
    for (; e < end; e++) {
        int c = d_col[e];
        float4 v = Z[c * 16 + slot];
        acc.x += v.x; acc.y += v.y; acc.z += v.z; acc.w += v.w;
    }

    ((float4*)d_h)[node * 16 + slot] = acc;

    int cb = slot * 4;
    atomicAdd(&sStat[cb + 0], acc.x);
    atomicAdd(&sStat[cb + 1], acc.y);
    atomicAdd(&sStat[cb + 2], acc.z);
    atomicAdd(&sStat[cb + 3], acc.w);
    atomicAdd(&sStat[HH + cb + 0], acc.x * acc.x);
    atomicAdd(&sStat[HH + cb + 1], acc.y * acc.y);
    atomicAdd(&sStat[HH + cb + 2], acc.z * acc.z);
    atomicAdd(&sStat[HH + cb + 3], acc.w * acc.w);
    __syncthreads();
    if (tid < 2 * HH) atomicAdd(&d_stats[tid], sStat[tid]);
}

// ---------------- GEMM B: x_next = relu( relu(BN(t)) @ W2 + b2 ); LAST -> pool ----------------
template<bool LAST>
__global__ __launch_bounds__(256)
void k_gemmB(const float* __restrict__ g, const float* __restrict__ bt,
             const float* __restrict__ W2, const float* __restrict__ b2) {
    __shared__ float sW[HH * HH];
    __shared__ float sSc[HH], sSh[HH], sB[HH];
    int tid = threadIdx.x;
    for (int i = tid; i < HH * HH; i += 256) sW[i] = W2[i];
    if (tid < HH) {
        float s = d_stats[tid], q = d_stats[HH + tid];
        float mean = s * (1.0f / NN);
        float var = q * (1.0f / NN) - mean * mean;
        float inv = rsqrtf(var + 1e-5f);
        float sc = g[tid] * inv;
        sSc[tid] = sc;
        sSh[tid] = bt[tid] - mean * sc;
        sB[tid] = b2[tid];
    }
    __syncthreads();

    int row = blockIdx.x * 256 + tid;
    if (row >= NN) return;

    float acc[HH];
#pragma unroll
    for (int c = 0; c < HH; c++) acc[c] = 0.f;

    const float4* Hr = (const float4*)(d_h + (size_t)row * HH);
#pragma unroll 1
    for (int kc = 0; kc < HH / 4; kc++) {
        float4 t4 = Hr[kc];
        int k0 = 4 * kc;
        float y0 = fmaxf(fmaf(t4.x, sSc[k0 + 0], sSh[k0 + 0]), 0.f);
        float y1 = fmaxf(fmaf(t4.y, sSc[k0 + 1], sSh[k0 + 1]), 0.f);
        float y2 = fmaxf(fmaf(t4.z, sSc[k0 + 2], sSh[k0 + 2]), 0.f);
        float y3 = fmaxf(fmaf(t4.w, sSc[k0 + 3], sSh[k0 + 3]), 0.f);
        const float* w0 = &sW[(k0 + 0) * HH];
        const float* w1 = &sW[(k0 + 1) * HH];
        const float* w2 = &sW[(k0 + 2) * HH];
        const float* w3 = &sW[(k0 + 3) * HH];
#pragma unroll
        for (int c = 0; c < HH; c++)
            acc[c] += y0 * w0[c] + y1 * w1[c] + y2 * w2[c] + y3 * w3[c];
    }

    if (LAST) {
        int gidx = d_batch32[row];
        float* pr = d_pool + gidx * HH;
#pragma unroll
        for (int c = 0; c < HH; c++) {
            float o = fmaxf(acc[c] + sB[c], 0.f);
            atomicAdd(pr + c, o);  // batch sorted -> mostly single-addr REDG per warp
        }
    } else {
        float4* Xr = (float4*)(d_x + (size_t)row * HH);
#pragma unroll
        for (int cc = 0; cc < HH / 4; cc++) {
            float4 o;
            o.x = fmaxf(acc[4 * cc + 0] + sB[4 * cc + 0], 0.f);
            o.y = fmaxf(acc[4 * cc + 1] + sB[4 * cc + 1], 0.f);
            o.z = fmaxf(acc[4 * cc + 2] + sB[4 * cc + 2], 0.f);
            o.w = fmaxf(acc[4 * cc + 3] + sB[4 * cc + 3], 0.f);
            Xr[cc] = o;
        }
    }
}

// ---------------- final MLP head: out = relu(pool @ fW1 + fb1) @ fW2 + fb2 ----------------
__global__ __launch_bounds__(256)
void k_final(const float* __restrict__ W1, const float* __restrict__ b1,
             const float* __restrict__ W2, const float* __restrict__ b2,
             float* __restrict__ out) {
    __shared__ float sW1[HH * HH];
    __shared__ float sW2[HH * DOUT];
    __shared__ float sB1[HH], sB2[DOUT];
    int tid = threadIdx.x;
    for (int i = tid; i < HH * HH; i += 256) sW1[i] = W1[i];
    for (int i = tid; i < HH * DOUT; i += 256) sW2[i] = W2[i];
    if (tid < HH) sB1[tid] = b1[tid];
    if (tid < DOUT) sB2[tid] = b2[tid];
    __syncthreads();

    int row = blockIdx.x * 256 + tid;
    if (row >= BB) return;

    float h[HH];
#pragma unroll
    for (int c = 0; c < HH; c++) h[c] = 0.f;
    const float4* P = (const float4*)(d_pool + row * HH);
#pragma unroll 1
    for (int kc = 0; kc < HH / 4; kc++) {
        float4 p = P[kc];
        int k0 = 4 * kc;
        const float* w0 = &sW1[(k0 + 0) * HH];
        const float* w1 = &sW1[(k0 + 1) * HH];
        const float* w2 = &sW1[(k0 + 2) * HH];
        const float* w3 = &sW1[(k0 + 3) * HH];
#pragma unroll
        for (int c = 0; c < HH; c++)
            h[c] += p.x * w0[c] + p.y * w1[c] + p.z * w2[c] + p.w * w3[c];
    }

    float o[DOUT];
#pragma unroll
    for (int c = 0; c < DOUT; c++) o[c] = 0.f;
#pragma unroll
    for (int k = 0; k < HH; k++) {
        float y = fmaxf(h[k] + sB1[k], 0.f);
#pragma unroll
        for (int c = 0; c < DOUT; c++) o[c] += y * sW2[k * DOUT + c];
    }
#pragma unroll
    for (int c = 0; c < DOUT; c++) out[row * DOUT + c] = o[c] + sB2[c];
}

// ---------------- launch ----------------
extern "C" void kernel_launch(void* const* d_in, const int* in_sizes, int n_in,
                              void* d_out, int out_size) {
    // identify the three data tensors by unique element counts (robust to order)
    int ix = 0, ie = 1, ib = 2;
    for (int i = 0; i < n_in; i++) {
        if (in_sizes[i] == NN * DIN) ix = i;        // x: 6.4M floats
        else if (in_sizes[i] == 2 * EE) ie = i;     // edge_index: 1.6M ints
        else if (in_sizes[i] == NN) ib = i;         // batch: 50K ints
    }
    const float* x = (const float*)d_in[ix];
    const void* ei = d_in[ie];
    const void* batch = d_in[ib];

    // locate c0_W1 (unique element count DIN*HH = 8192); robust to whether the
    // scalar batch_size appears as an input. Subsequent params are positional.
    int base = -1;
    for (int i = 1; i < n_in; i++) {
        if (in_sizes[i] == DIN * HH) { base = i; break; }
    }
    if (base < 0) base = 4;
    auto F = [&](int i) { return (const float*)d_in[base + i]; };
    // per-conv params: W1, b1, g1, bt1, W2, b2  (b1 cancels through BN -> unused)

    const int GROWS = (NN + 255) / 256;   // 196
    const int GE = (EE + 255) / 256;      // 3125

    k_detect<<<1, 1>>>(ei);
    k_cvt<<<GE, 256>>>(ei, batch);
    k_zero<<<GROWS, 256>>>();
    k_hist<<<GE, 256>>>();
    k_scan<<<1, 1024>>>();
    k_fill<<<GE, 256>>>();

    // layer 0 (IN=128)
    k_gemmA<DIN, true><<<GROWS, 256>>>(x, F(0));
    k_agg<<<(NN * 16) / 256, 256>>>();
    k_gemmB<false><<<GROWS, 256>>>(F(2), F(3), F(4), F(5));

    // layer 1
    k_gemmA<HH, false><<<GROWS, 256>>>(nullptr, F(6));
    k_agg<<<(NN * 16) / 256, 256>>>();
    k_gemmB<false><<<GROWS, 256>>>(F(8), F(9), F(10), F(11));

    // layer 2 (fused pooling)
    k_gemmA<HH, false><<<GROWS, 256>>>(nullptr, F(12));
    k_agg<<<(NN * 16) / 256, 256>>>();
    k_gemmB<true><<<GROWS, 256>>>(F(14), F(15), F(16), F(17));

    k_final<<<2, 256>>>(F(18), F(19), F(20), F(21), (float*)d_out);
}

// round 12
// speedup vs baseline: 1.0916x; 1.0916x over previous
#include <cuda_runtime.h>
#include <cstdint>

#define NN   50000
#define EE   800000
#define BB   512
#define DIN  128
#define HH   64
#define DOUT 32

// ---------------- scratch (static device arrays; no allocation) ----------------
__device__ __align__(16) float d_z[NN * HH];    // z = x @ W1 (pre-aggregation)
__device__ __align__(16) float d_h[NN * HH];    // t = z_self + sum_nbr z (pre-BN)
__device__ __align__(16) float d_x[NN * HH];    // layer output
__device__ __align__(16) float d_pool[BB * HH]; // global add pool
__device__ __align__(16) float d_stats[2 * HH]; // colsum | colsumsq of t
__device__ int   d_deg[NN];
__device__ int   d_off[NN + 1];
__device__ int   d_cur[NN];
__device__ int   d_col[EE];         // CSR: src ids grouped by dst
__device__ int   d_src32[EE];       // normalized int32 edge endpoints
__device__ int   d_dst32[EE];
__device__ int   d_batch32[NN];     // normalized int32 graph ids

__device__ __forceinline__ int clampi(int v, int hi) {
    return v < 0 ? 0 : (v >= hi ? hi - 1 : v);
}

// ---------------- zero pass (must precede k_cvt: it histograms into d_deg) ----
__global__ void k_zero() {
    int i = blockIdx.x * 256 + threadIdx.x;
    if (i < NN) d_deg[i] = 0;
    if (i < BB * HH) d_pool[i] = 0.f;
}

// ---------------- dtype detect + normalize + degree histogram (fused) --------
// JAX may silently downcast the reference's int64 indices to int32. Detect per
// thread from a 16-value broadcast read: genuine int64 ids are < NN (high
// words 0); packed int32 pairs read as int64 are >= 2^32 when the odd element
// is nonzero (P[16 consecutive zeros] ~ (2e-5)^16 ~ 0).
__global__ void k_cvt(const void* __restrict__ ei, const void* __restrict__ batch) {
    const long long* p64 = (const long long*)ei;
    int is64 = 1;
#pragma unroll
    for (int j = 0; j < 16; j++) {
        long long v = p64[j];
        if (v < 0 || v >= NN) { is64 = 0; break; }
    }
    int i = blockIdx.x * 256 + threadIdx.x;
    if (i < EE) {
        int s, d;
        if (is64) {
            s = (int)p64[i];
            d = (int)p64[EE + i];
        } else {
            s = ((const int*)ei)[i];
            d = ((const int*)ei)[EE + i];
        }
        s = clampi(s, NN);          // no-op on valid data; prevents OOB on bad parse
        d = clampi(d, NN);
        d_src32[i] = s;
        d_dst32[i] = d;
        atomicAdd(&d_deg[d], 1);    // fused histogram
    }
    if (i < NN) {
        int b = is64 ? (int)((const long long*)batch)[i]
                     : ((const int*)batch)[i];
        d_batch32[i] = clampi(b, BB);
    }
}

__global__ void k_scan() {
    __shared__ int ssum[1024];
    int t = threadIdx.x;
    const int CH = (NN + 1023) / 1024;  // 49
    int start = t * CH;
    int s = 0;
    for (int i = 0; i < CH; i++) {
        int idx = start + i;
        if (idx < NN) s += d_deg[idx];
    }
    ssum[t] = s;
    __syncthreads();
    for (int off = 1; off < 1024; off <<= 1) {
        int v = (t >= off) ? ssum[t - off] : 0;
        __syncthreads();
        ssum[t] += v;
        __syncthreads();
    }
    int run = (t == 0) ? 0 : ssum[t - 1];
    for (int i = 0; i < CH; i++) {
        int idx = start + i;
        if (idx < NN) {
            d_off[idx] = run;
            d_cur[idx] = run;
            run += d_deg[idx];
        }
    }
    if (t == 1023) d_off[NN] = run;
}

__global__ void k_fill() {
    int e = blockIdx.x * 256 + threadIdx.x;
    if (e < EE) {
        int d = d_dst32[e];
        int p = atomicAdd(&d_cur[d], 1);
        d_col[p] = d_src32[e];
    }
}

// ---------------- GEMM A: z = x @ W1  (bias b1 cancels through BN) ----------------
// 128-thread CTAs, 391 blocks: better wave balance than 196x256.
template<int K, bool FROM_PARAM>
__global__ __launch_bounds__(128)
void k_gemmA(const float* __restrict__ xp, const float* __restrict__ W) {
    __shared__ float sW[K * HH];
    int tid = threadIdx.x;
    for (int i = tid; i < K * HH; i += 128) sW[i] = W[i];
    if (blockIdx.x == 0 && tid < 2 * HH) d_stats[tid] = 0.f;  // reset stats for this layer
    __syncthreads();

    int row = blockIdx.x * 128 + tid;
    if (row >= NN) return;
    const float* X = FROM_PARAM ? xp : d_x;

    float acc[HH];
#pragma unroll
    for (int c = 0; c < HH; c++) acc[c] = 0.f;

    const float4* Xr = (const float4*)(X + (size_t)row * K);
#pragma unroll 1
    for (int kc = 0; kc < K / 4; kc++) {
        float4 a = Xr[kc];
        const float* w0 = &sW[(4 * kc + 0) * HH];
        const float* w1 = &sW[(4 * kc + 1) * HH];
        const float* w2 = &sW[(4 * kc + 2) * HH];
        const float* w3 = &sW[(4 * kc + 3) * HH];
#pragma unroll
        for (int c = 0; c < HH; c++)
            acc[c] += a.x * w0[c] + a.y * w1[c] + a.z * w2[c] + a.w * w3[c];
    }

    float4* Zr = (float4*)(d_z + (size_t)row * HH);
#pragma unroll
    for (int cc = 0; cc < HH / 4; cc++)
        Zr[cc] = make_float4(acc[4 * cc], acc[4 * cc + 1], acc[4 * cc + 2], acc[4 * cc + 3]);
}

// ---------------- aggregation: t = z_self + sum_nbr z, plus BN stats ----------------
// 16 lanes per node (64 floats = 16 x float4 slots); grid = NN*16/256 = 3125 exact.
__global__ __launch_bounds__(256)
void k_agg() {
    __shared__ float sStat[2 * HH];
    int tid = threadIdx.x;
    if (tid < 2 * HH) sStat[tid] = 0.f;
    __syncthreads();

    int gt = blockIdx.x * 256 + tid;
    int node = gt >> 4;
    int slot = gt & 15;

    const float4* Z = (const float4*)d_z;
    float4 acc = Z[node * 16 + slot];  // self term (eps = 0)

    int e = d_off[node];
    int end = d_off[node + 1];
    for (; e + 3 < end; e += 4) {
        int c0 = d_col[e], c1 = d_col[e + 1], c2 = d_col[e + 2], c3 = d_col[e + 3];
        float4 v0 = Z[c0 * 16 + slot];
        float4 v1 = Z[c1 * 16 + slot];
        float4 v2 = Z[c2 * 16 + slot];
        float4 v3 = Z[c3 * 16 + slot];
        acc.x += (v0.x + v1.x) + (v2.x + v3.x);
        acc.y += (v0.y + v1.y) + (v2.y + v3.y);
        acc.z += (v0.z + v1.z) + (v2.z + v3.z);
        acc.w += (v0.w + v1.w) + (v2.w + v3.w);
    }
    for (; e < end; e++) {
        int c = d_col[e];
        float4 v = Z[c * 16 + slot];
        acc.x += v.x; acc.y += v.y; acc.z += v.z; acc.w += v.w;
    }

    ((float4*)d_h)[node * 16 + slot] = acc;

    int cb = slot * 4;
    atomicAdd(&sStat[cb + 0], acc.x);
    atomicAdd(&sStat[cb + 1], acc.y);
    atomicAdd(&sStat[cb + 2], acc.z);
    atomicAdd(&sStat[cb + 3], acc.w);
    atomicAdd(&sStat[HH + cb + 0], acc.x * acc.x);
    atomicAdd(&sStat[HH + cb + 1], acc.y * acc.y);
    atomicAdd(&sStat[HH + cb + 2], acc.z * acc.z);
    atomicAdd(&sStat[HH + cb + 3], acc.w * acc.w);
    __syncthreads();
    if (tid < 2 * HH) atomicAdd(&d_stats[tid], sStat[tid]);
}

// ---------------- GEMM B: x_next = relu( relu(BN(t)) @ W2 + b2 ); LAST -> pool ----------------
template<bool LAST>
__global__ __launch_bounds__(128)
void k_gemmB(const float* __restrict__ g, const float* __restrict__ bt,
             const float* __restrict__ W2, const float* __restrict__ b2) {
    __shared__ float sW[HH * HH];
    __shared__ float sSc[HH], sSh[HH], sB[HH];
    int tid = threadIdx.x;
    for (int i = tid; i < HH * HH; i += 128) sW[i] = W2[i];
    if (tid < HH) {
        float s = d_stats[tid], q = d_stats[HH + tid];
        float mean = s * (1.0f / NN);
        float var = q * (1.0f / NN) - mean * mean;
        float inv = rsqrtf(var + 1e-5f);
        float sc = g[tid] * inv;
        sSc[tid] = sc;
        sSh[tid] = bt[tid] - mean * sc;
        sB[tid] = b2[tid];
    }
    __syncthreads();

    int row = blockIdx.x * 128 + tid;
    if (row >= NN) return;

    float acc[HH];
#pragma unroll
    for (int c = 0; c < HH; c++) acc[c] = 0.f;

    const float4* Hr = (const float4*)(d_h + (size_t)row * HH);
#pragma unroll 1
    for (int kc = 0; kc < HH / 4; kc++) {
        float4 t4 = Hr[kc];
        int k0 = 4 * kc;
        float y0 = fmaxf(fmaf(t4.x, sSc[k0 + 0], sSh[k0 + 0]), 0.f);
        float y1 = fmaxf(fmaf(t4.y, sSc[k0 + 1], sSh[k0 + 1]), 0.f);
        float y2 = fmaxf(fmaf(t4.z, sSc[k0 + 2], sSh[k0 + 2]), 0.f);
        float y3 = fmaxf(fmaf(t4.w, sSc[k0 + 3], sSh[k0 + 3]), 0.f);
        const float* w0 = &sW[(k0 + 0) * HH];
        const float* w1 = &sW[(k0 + 1) * HH];
        const float* w2 = &sW[(k0 + 2) * HH];
        const float* w3 = &sW[(k0 + 3) * HH];
#pragma unroll
        for (int c = 0; c < HH; c++)
            acc[c] += y0 * w0[c] + y1 * w1[c] + y2 * w2[c] + y3 * w3[c];
    }

    if (LAST) {
        int gidx = d_batch32[row];
        float* pr = d_pool + gidx * HH;
#pragma unroll
        for (int c = 0; c < HH; c++) {
            float o = fmaxf(acc[c] + sB[c], 0.f);
            atomicAdd(pr + c, o);  // warp-uniform addr -> HW REDUX-aggregated
        }
    } else {
        float4* Xr = (float4*)(d_x + (size_t)row * HH);
#pragma unroll
        for (int cc = 0; cc < HH / 4; cc++) {
            float4 o;
            o.x = fmaxf(acc[4 * cc + 0] + sB[4 * cc + 0], 0.f);
            o.y = fmaxf(acc[4 * cc + 1] + sB[4 * cc + 1], 0.f);
            o.z = fmaxf(acc[4 * cc + 2] + sB[4 * cc + 2], 0.f);
            o.w = fmaxf(acc[4 * cc + 3] + sB[4 * cc + 3], 0.f);
            Xr[cc] = o;
        }
    }
}

// ---------------- final MLP head: out = relu(pool @ fW1 + fb1) @ fW2 + fb2 ----------------
__global__ __launch_bounds__(128)
void k_final(const float* __restrict__ W1, const float* __restrict__ b1,
             const float* __restrict__ W2, const float* __restrict__ b2,
             float* __restrict__ out) {
    __shared__ float sW1[HH * HH];
    __shared__ float sW2[HH * DOUT];
    __shared__ float sB1[HH], sB2[DOUT];
    int tid = threadIdx.x;
    for (int i = tid; i < HH * HH; i += 128) sW1[i] = W1[i];
    for (int i = tid; i < HH * DOUT; i += 128) sW2[i] = W2[i];
    if (tid < HH) sB1[tid] = b1[tid];
    if (tid < DOUT) sB2[tid] = b2[tid];
    __syncthreads();

    int row = blockIdx.x * 128 + tid;
    if (row >= BB) return;

    float h[HH];
#pragma unroll
    for (int c = 0; c < HH; c++) h[c] = 0.f;
    const float4* P = (const float4*)(d_pool + row * HH);
#pragma unroll 1
    for (int kc = 0; kc < HH / 4; kc++) {
        float4 p = P[kc];
        int k0 = 4 * kc;
        const float* w0 = &sW1[(k0 + 0) * HH];
        const float* w1 = &sW1[(k0 + 1) * HH];
        const float* w2 = &sW1[(k0 + 2) * HH];
        const float* w3 = &sW1[(k0 + 3) * HH];
#pragma unroll
        for (int c = 0; c < HH; c++)
            h[c] += p.x * w0[c] + p.y * w1[c] + p.z * w2[c] + p.w * w3[c];
    }

    float o[DOUT];
#pragma unroll
    for (int c = 0; c < DOUT; c++) o[c] = 0.f;
#pragma unroll
    for (int k = 0; k < HH; k++) {
        float y = fmaxf(h[k] + sB1[k], 0.f);
#pragma unroll
        for (int c = 0; c < DOUT; c++) o[c] += y * sW2[k * DOUT + c];
    }
#pragma unroll
    for (int c = 0; c < DOUT; c++) out[row * DOUT + c] = o[c] + sB2[c];
}

// ---------------- launch ----------------
extern "C" void kernel_launch(void* const* d_in, const int* in_sizes, int n_in,
                              void* d_out, int out_size) {
    // identify the three data tensors by unique element counts (robust to order)
    int ix = 0, ie = 1, ib = 2;
    for (int i = 0; i < n_in; i++) {
        if (in_sizes[i] == NN * DIN) ix = i;        // x: 6.4M floats
        else if (in_sizes[i] == 2 * EE) ie = i;     // edge_index: 1.6M ints
        else if (in_sizes[i] == NN) ib = i;         // batch: 50K ints
    }
    const float* x = (const float*)d_in[ix];
    const void* ei = d_in[ie];
    const void* batch = d_in[ib];

    // locate c0_W1 (unique element count DIN*HH = 8192); params positional after it
    int base = -1;
    for (int i = 1; i < n_in; i++) {
        if (in_sizes[i] == DIN * HH) { base = i; break; }
    }
    if (base < 0) base = 4;
    auto F = [&](int i) { return (const float*)d_in[base + i]; };
    // per-conv params: W1, b1, g1, bt1, W2, b2  (b1 cancels through BN -> unused)

    const int GZ = (NN + 255) / 256;      // 196 (zero pass)
    const int GE = (EE + 255) / 256;      // 3125
    const int GR = (NN + 127) / 128;      // 391 (GEMM-family, balanced)

    k_zero<<<GZ, 256>>>();
    k_cvt<<<GE, 256>>>(ei, batch);        // detect + normalize + histogram
    k_scan<<<1, 1024>>>();
    k_fill<<<GE, 256>>>();

    // layer 0 (IN=128)
    k_gemmA<DIN, true><<<GR, 128>>>(x, F(0));
    k_agg<<<(NN * 16) / 256, 256>>>();
    k_gemmB<false><<<GR, 128>>>(F(2), F(3), F(4), F(5));

    // layer 1
    k_gemmA<HH, false><<<GR, 128>>>(nullptr, F(6));
    k_agg<<<(NN * 16) / 256, 256>>>();
    k_gemmB<false><<<GR, 128>>>(F(8), F(9), F(10), F(11));

    // layer 2 (fused pooling)
    k_gemmA<HH, false><<<GR, 128>>>(nullptr, F(12));
    k_agg<<<(NN * 16) / 256, 256>>>();
    k_gemmB<true><<<GR, 128>>>(F(14), F(15), F(16), F(17));

    k_final<<<(BB + 127) / 128, 128>>>(F(18), F(19), F(20), F(21), (float*)d_out);
}